// round 1
// baseline (speedup 1.0000x reference)
#include <cuda_runtime.h>

// SparseGapPerSpecies: e_atom = (x^T A_s x)/(x.x), A_s = Y_s^T diag(w/|y|^2) Y_s
// then segment-sum by structure id.
//
// Inputs (metadata order):
//  0: power_spectrum  f32 [N_ATOMS, 512]
//  1: support_points  f32 [4, 1000, 512]
//  2: weights         f32 [4, 1000]
//  3: all_species     i32 [N_ATOMS]
//  4: structure_ids   i32 [N_ATOMS]
//  (5: num_structures - unused; out_size gives it)
// Output: f32 [n_structures, 1]

#define N_SPECIES   4
#define N_FEAT      512
#define MAX_ATOMS   100352
#define MAX_SUPPORT 1024

__device__ float g_A[N_SPECIES * N_FEAT * N_FEAT];   // 4 MB scratch
__device__ float g_c[N_SPECIES * MAX_SUPPORT];
__device__ int   g_order[MAX_ATOMS];
__device__ int   g_cnt[N_SPECIES];
__device__ int   g_off[N_SPECIES + 1];
__device__ int   g_cur[N_SPECIES];

typedef unsigned long long ull;

__device__ __forceinline__ ull pk2(float v) {
    ull r; unsigned u = __float_as_uint(v);
    asm("mov.b64 %0, {%1, %1};" : "=l"(r) : "r"(u));
    return r;
}
__device__ __forceinline__ ull fma2(ull a, ull b, ull c) {
    ull d;
    asm("fma.rn.f32x2 %0, %1, %2, %3;" : "=l"(d) : "l"(a), "l"(b), "l"(c));
    return d;
}

// ---------------- init: zero output + species counters ----------------
__global__ void k_init(float* out, int n_out) {
    int i = blockIdx.x * 256 + threadIdx.x;
    if (i < n_out) out[i] = 0.f;
    if (i < N_SPECIES) g_cnt[i] = 0;
}

// ---------------- per-support scale c = w / |y|^2 ----------------
__global__ void k_prep_c(const float* __restrict__ sp, const float* __restrict__ w,
                         int n_support) {
    int b = blockIdx.x;
    int s = b / n_support, m = b % n_support;
    const float* y = sp + (size_t)(s * n_support + m) * N_FEAT;
    float acc = 0.f;
    for (int i = threadIdx.x; i < N_FEAT; i += 128) { float v = y[i]; acc += v * v; }
    #pragma unroll
    for (int o = 16; o; o >>= 1) acc += __shfl_xor_sync(0xffffffffu, acc, o);
    __shared__ float r[4];
    if ((threadIdx.x & 31) == 0) r[threadIdx.x >> 5] = acc;
    __syncthreads();
    if (threadIdx.x == 0) {
        float t = r[0] + r[1] + r[2] + r[3];
        g_c[s * MAX_SUPPORT + m] = w[s * n_support + m] / t;
    }
}

// ---------------- species histogram / offsets / scatter ----------------
__global__ void k_count(const int* __restrict__ spc, int n) {
    int i = blockIdx.x * 256 + threadIdx.x;
    if (i < n) atomicAdd(&g_cnt[spc[i]], 1);
}
__global__ void k_off() {
    if (threadIdx.x == 0) {
        int acc = 0;
        for (int s = 0; s < N_SPECIES; ++s) { g_off[s] = acc; g_cur[s] = acc; acc += g_cnt[s]; }
        g_off[N_SPECIES] = acc;
    }
}
__global__ void k_scatter(const int* __restrict__ spc, int n) {
    int i = blockIdx.x * 256 + threadIdx.x;
    if (i < n) { int p = atomicAdd(&g_cur[spc[i]], 1); g_order[p] = i; }
}

// ---------------- A_s = Y^T diag(c) Y  (per species 512x512, K=1000) ----------------
__global__ __launch_bounds__(256) void k_computeA(const float* __restrict__ sp, int n_support) {
    int s = blockIdx.z;
    int i0 = blockIdx.y * 64, j0 = blockIdx.x * 64;
    __shared__ float Yi[16][64];
    __shared__ float Yj[16][64];
    int tid = threadIdx.x;
    int ty = tid >> 4, tx = tid & 15;
    float acc[4][4];
    #pragma unroll
    for (int a = 0; a < 4; ++a)
        #pragma unroll
        for (int b = 0; b < 4; ++b) acc[a][b] = 0.f;

    const float* Y = sp + (size_t)s * n_support * N_FEAT;
    const float* c = g_c + s * MAX_SUPPORT;

    for (int m0 = 0; m0 < n_support; m0 += 16) {
        #pragma unroll
        for (int it = 0; it < 4; ++it) {
            int idx = it * 256 + tid;
            int kk = idx >> 6, col = idx & 63;
            int m = m0 + kk;
            float yi = 0.f, yj = 0.f, cm = 0.f;
            if (m < n_support) {
                cm = c[m];
                yi = Y[(size_t)m * N_FEAT + i0 + col];
                yj = Y[(size_t)m * N_FEAT + j0 + col];
            }
            Yi[kk][col] = cm * yi;
            Yj[kk][col] = yj;
        }
        __syncthreads();
        #pragma unroll
        for (int kk = 0; kk < 16; ++kk) {
            float a[4], b[4];
            #pragma unroll
            for (int ii = 0; ii < 4; ++ii) a[ii] = Yi[kk][ty * 4 + ii];
            #pragma unroll
            for (int jj = 0; jj < 4; ++jj) b[jj] = Yj[kk][tx * 4 + jj];
            #pragma unroll
            for (int ii = 0; ii < 4; ++ii)
                #pragma unroll
                for (int jj = 0; jj < 4; ++jj) acc[ii][jj] += a[ii] * b[jj];
        }
        __syncthreads();
    }
    float* Ad = g_A + (size_t)s * N_FEAT * N_FEAT;
    #pragma unroll
    for (int ii = 0; ii < 4; ++ii)
        #pragma unroll
        for (int jj = 0; jj < 4; ++jj)
            Ad[(size_t)(i0 + ty * 4 + ii) * N_FEAT + (j0 + tx * 4 + jj)] = acc[ii][jj];
}

// ---------------- main: per 64-atom species-uniform tile ----------------
// Q = X @ A_s (M=64, N=512, K=512), fused e = rowdot(Q, X), /|x|^2, atomic segment sum.
// 256 threads: tm = tid>>5 (8 m-groups of 8 atoms), tn = tid&31 (32 n-groups of 4 cols).
// Accumulators are f32x2 pairs over adjacent atoms -> packed FFMA2.
#define XPITCH 66   // 512-row X^T tile, padded; rows 264B (8B aligned, conflict-light)

__global__ __launch_bounds__(256, 1) void k_main(const float* __restrict__ ps,
                                                 const int* __restrict__ sids,
                                                 float* __restrict__ out) {
    extern __shared__ float smf[];
    float* XsT   = smf;                         // [512][66]
    float* As    = smf + N_FEAT * XPITCH;       // [2][16][128]
    float* nrm   = As + 2 * 16 * 128;           // [64]
    int*  sid_sm = (int*)(nrm + 64);            // [64]
    int*  aidx   = sid_sm + 64;                 // [64]

    const int tid = threadIdx.x;
    const int s = blockIdx.y;
    const int off0 = g_off[s], off1 = g_off[s + 1];
    const int base = off0 + blockIdx.x * 64;
    if (base >= off1) return;
    const int valid = min(64, off1 - base);

    if (tid < 64) {
        nrm[tid] = 0.f;
        int ai = (tid < valid) ? g_order[base + tid] : -1;
        aidx[tid] = ai;
        sid_sm[tid] = (ai >= 0) ? sids[ai] : 0;
    }
    __syncthreads();

    // gather + transpose 64 atom rows into SMEM: XsT[k][a]
    #pragma unroll 8
    for (int it = 0; it < 128; ++it) {
        int e = it * 256 + tid;
        int a = e >> 9;          // /512
        int k = e & 511;
        int ai = aidx[a];
        XsT[k * XPITCH + a] = (ai >= 0) ? ps[(size_t)ai * N_FEAT + k] : 0.f;
    }
    __syncthreads();

    // |x|^2 per atom
    {
        int a = tid & 63, seg = tid >> 6;
        float acc = 0.f;
        #pragma unroll 8
        for (int k = seg * 128; k < seg * 128 + 128; ++k) {
            float v = XsT[k * XPITCH + a];
            acc += v * v;
        }
        atomicAdd(&nrm[a], acc);
    }
    // (sync provided by first prefetch barrier below)

    const float* Am = g_A + (size_t)s * N_FEAT * N_FEAT;
    const int tm = tid >> 5;
    const int tn = tid & 31;

    float part[8];
    #pragma unroll
    for (int i = 0; i < 8; ++i) part[i] = 0.f;

    for (int n0 = 0; n0 < N_FEAT; n0 += 128) {
        ull acc[4][4];
        #pragma unroll
        for (int p = 0; p < 4; ++p)
            #pragma unroll
            for (int j = 0; j < 4; ++j) acc[p][j] = 0ull;

        float r[8];
        // prefetch K-chunk 0
        #pragma unroll
        for (int it = 0; it < 8; ++it) {
            int idx = it * 256 + tid; int kk = idx >> 7, col = idx & 127;
            r[it] = Am[(size_t)kk * N_FEAT + n0 + col];
        }
        #pragma unroll
        for (int it = 0; it < 8; ++it) {
            int idx = it * 256 + tid; int kk = idx >> 7, col = idx & 127;
            As[kk * 128 + col] = r[it];
        }
        __syncthreads();

        for (int c = 0; c < 32; ++c) {
            int cur = c & 1;
            const float* curb = As + cur * 2048;
            float* nxtb = As + (cur ^ 1) * 2048;
            bool more = (c + 1 < 32);
            if (more) {
                int k0n = (c + 1) * 16;
                #pragma unroll
                for (int it = 0; it < 8; ++it) {
                    int idx = it * 256 + tid; int kk = idx >> 7, col = idx & 127;
                    r[it] = Am[(size_t)(k0n + kk) * N_FEAT + n0 + col];
                }
            }
            int k0 = c * 16;
            #pragma unroll
            for (int kk = 0; kk < 16; ++kk) {
                const float* xr = XsT + (k0 + kk) * XPITCH + tm * 8;
                ull x[4];
                x[0] = *(const ull*)(xr + 0);
                x[1] = *(const ull*)(xr + 2);
                x[2] = *(const ull*)(xr + 4);
                x[3] = *(const ull*)(xr + 6);
                const float4 a4 = *(const float4*)(curb + kk * 128 + tn * 4);
                ull ap[4];
                ap[0] = pk2(a4.x); ap[1] = pk2(a4.y); ap[2] = pk2(a4.z); ap[3] = pk2(a4.w);
                #pragma unroll
                for (int p = 0; p < 4; ++p)
                    #pragma unroll
                    for (int j = 0; j < 4; ++j)
                        acc[p][j] = fma2(x[p], ap[j], acc[p][j]);
            }
            if (more) {
                #pragma unroll
                for (int it = 0; it < 8; ++it) {
                    int idx = it * 256 + tid; int kk = idx >> 7, col = idx & 127;
                    nxtb[kk * 128 + col] = r[it];
                }
            }
            __syncthreads();
        }

        // fuse e += Q .* X over this column block
        #pragma unroll
        for (int j = 0; j < 4; ++j) {
            int jj = n0 + tn * 4 + j;
            const float* xc = XsT + jj * XPITCH + tm * 8;
            #pragma unroll
            for (int p = 0; p < 4; ++p) {
                float qlo = __uint_as_float((unsigned)(acc[p][j] & 0xffffffffull));
                float qhi = __uint_as_float((unsigned)(acc[p][j] >> 32));
                part[2 * p]     += qlo * xc[2 * p];
                part[2 * p + 1] += qhi * xc[2 * p + 1];
            }
        }
        __syncthreads();
    }

    // warp tm owns atoms [tm*8, tm*8+8): reduce across tn lanes, emit
    #pragma unroll
    for (int i = 0; i < 8; ++i) {
        float v = part[i];
        #pragma unroll
        for (int o = 16; o; o >>= 1) v += __shfl_xor_sync(0xffffffffu, v, o);
        if (tn == 0) {
            int m = tm * 8 + i;
            if (m < valid) atomicAdd(&out[sid_sm[m]], v / nrm[m]);
        }
    }
}

// ---------------- launch ----------------
extern "C" void kernel_launch(void* const* d_in, const int* in_sizes, int n_in,
                              void* d_out, int out_size) {
    const float* ps   = (const float*)d_in[0];
    const float* sp   = (const float*)d_in[1];
    const float* w    = (const float*)d_in[2];
    const int*   spec = (const int*)d_in[3];
    const int*   sids = (const int*)d_in[4];
    float* out = (float*)d_out;

    int n_atoms   = in_sizes[3];
    int n_support = in_sizes[2] / N_SPECIES;

    const int smem_main = (N_FEAT * XPITCH + 2 * 16 * 128 + 64) * (int)sizeof(float)
                        + 128 * (int)sizeof(int);
    cudaFuncSetAttribute(k_main, cudaFuncAttributeMaxDynamicSharedMemorySize, smem_main);

    int init_n = out_size > N_SPECIES ? out_size : N_SPECIES;
    k_init<<<(init_n + 255) / 256, 256>>>(out, out_size);
    k_prep_c<<<N_SPECIES * n_support, 128>>>(sp, w, n_support);
    k_count<<<(n_atoms + 255) / 256, 256>>>(spec, n_atoms);
    k_off<<<1, 32>>>();
    k_scatter<<<(n_atoms + 255) / 256, 256>>>(spec, n_atoms);
    k_computeA<<<dim3(N_FEAT / 64, N_FEAT / 64, N_SPECIES), 256>>>(sp, n_support);

    dim3 grid((n_atoms + 63) / 64, N_SPECIES);
    k_main<<<grid, 256, smem_main>>>(ps, sids, out);
}

// round 3
// speedup vs baseline: 2.5177x; 2.5177x over previous
#include <cuda_runtime.h>
#include <cuda_bf16.h>
#include <stdint.h>

// SparseGapPerSpecies via quadratic form + warp-level bf16 MMA (split hi/lo):
//   A_s = Y_s^T diag(w/|y|^2) Y_s   (512x512/species, fp32 -> bf16 hi+lo)
//   Q = X A_s  via mma.sync m16n8k16 (3 split terms, fp32 accum in regs)
//   e_atom = rowdot(Q, X)/|x|^2 ; energy = segment_sum(e_atom)
// NOTE: no tcgen05/TMA — harness ptxas targets plain sm_103 (no 'a' features).

#define N_SPECIES   4
#define N_FEAT      512
#define MAX_ATOMS   100352
#define MAX_SUPPORT 1024
#define MT          128     // atoms per block
#define NC          128     // n-chunk cols
#define KC          64      // k-chunk

__device__ __nv_bfloat16 g_Ah[N_SPECIES * N_FEAT * N_FEAT];  // [s][k][n]
__device__ __nv_bfloat16 g_Al[N_SPECIES * N_FEAT * N_FEAT];
__device__ __nv_bfloat16 g_Xh[(size_t)MAX_ATOMS * N_FEAT];   // sorted by species
__device__ __nv_bfloat16 g_Xl[(size_t)MAX_ATOMS * N_FEAT];
__device__ float g_invn[MAX_ATOMS];
__device__ int   g_sidp[MAX_ATOMS];
__device__ float g_c[N_SPECIES * MAX_SUPPORT];
__device__ int   g_order[MAX_ATOMS];
__device__ int   g_cnt[N_SPECIES];
__device__ int   g_off[N_SPECIES + 1];
__device__ int   g_cur[N_SPECIES];

// ---------------- PTX helpers (sm_80-level only) ----------------
__device__ __forceinline__ uint32_t smem_u32(const void* p) {
    uint32_t a;
    asm("{ .reg .u64 t; cvta.to.shared.u64 t, %1; cvt.u32.u64 %0, t; }" : "=r"(a) : "l"(p));
    return a;
}
__device__ __forceinline__ void cpasync16(uint32_t dst, const void* src) {
    asm volatile("cp.async.cg.shared.global [%0], [%1], 16;" :: "r"(dst), "l"(src) : "memory");
}
#define CP_COMMIT() asm volatile("cp.async.commit_group;" ::: "memory")

__device__ __forceinline__ void ldsm_x4(uint32_t* r, uint32_t a) {
    asm volatile("ldmatrix.sync.aligned.m8n8.x4.shared.b16 {%0,%1,%2,%3}, [%4];"
                 : "=r"(r[0]), "=r"(r[1]), "=r"(r[2]), "=r"(r[3]) : "r"(a));
}
__device__ __forceinline__ void ldsm_x4t(uint32_t* r, uint32_t a) {
    asm volatile("ldmatrix.sync.aligned.m8n8.x4.trans.shared.b16 {%0,%1,%2,%3}, [%4];"
                 : "=r"(r[0]), "=r"(r[1]), "=r"(r[2]), "=r"(r[3]) : "r"(a));
}
__device__ __forceinline__ void mma16816(float* c, const uint32_t* a, const uint32_t* b) {
    asm volatile("mma.sync.aligned.m16n8k16.row.col.f32.bf16.bf16.f32 "
                 "{%0,%1,%2,%3},{%4,%5,%6,%7},{%8,%9},{%0,%1,%2,%3};"
                 : "+f"(c[0]), "+f"(c[1]), "+f"(c[2]), "+f"(c[3])
                 : "r"(a[0]), "r"(a[1]), "r"(a[2]), "r"(a[3]), "r"(b[0]), "r"(b[1]));
}
__device__ __forceinline__ uint32_t pkbf(float a, float b) {
    __nv_bfloat162 t = __floats2bfloat162_rn(a, b);
    return *(uint32_t*)&t;
}

// ---------------- small prep kernels ----------------
__global__ void k_init(float* out, int n_out) {
    int i = blockIdx.x * 256 + threadIdx.x;
    if (i < n_out) out[i] = 0.f;
    if (i < N_SPECIES) g_cnt[i] = 0;
}
__global__ void k_prep_c(const float* __restrict__ sp, const float* __restrict__ w,
                         int n_support) {
    int b = blockIdx.x;
    int s = b / n_support, m = b % n_support;
    const float* y = sp + (size_t)(s * n_support + m) * N_FEAT;
    float acc = 0.f;
    for (int i = threadIdx.x; i < N_FEAT; i += 128) { float v = y[i]; acc += v * v; }
    #pragma unroll
    for (int o = 16; o; o >>= 1) acc += __shfl_xor_sync(0xffffffffu, acc, o);
    __shared__ float r[4];
    if ((threadIdx.x & 31) == 0) r[threadIdx.x >> 5] = acc;
    __syncthreads();
    if (threadIdx.x == 0)
        g_c[s * MAX_SUPPORT + m] = w[s * n_support + m] / (r[0] + r[1] + r[2] + r[3]);
}
__global__ void k_count(const int* __restrict__ spc, int n) {
    int i = blockIdx.x * 256 + threadIdx.x;
    if (i < n) atomicAdd(&g_cnt[spc[i]], 1);
}
__global__ void k_off() {
    if (threadIdx.x == 0) {
        int acc = 0;
        for (int s = 0; s < N_SPECIES; ++s) { g_off[s] = acc; g_cur[s] = acc; acc += g_cnt[s]; }
        g_off[N_SPECIES] = acc;
    }
}
__global__ void k_scatter(const int* __restrict__ spc, int n) {
    int i = blockIdx.x * 256 + threadIdx.x;
    if (i < n) { int p = atomicAdd(&g_cur[spc[i]], 1); g_order[p] = i; }
}

// ---------------- prep X: gather sorted rows, split bf16 hi/lo, norms ----------------
__global__ __launch_bounds__(256) void k_prepX(const float* __restrict__ ps,
                                               const int* __restrict__ sids, int n) {
    int wid = threadIdx.x >> 5, lid = threadIdx.x & 31;
    int p = blockIdx.x * 8 + wid;
    if (p >= n) return;
    int ai = g_order[p];
    const float4* src = (const float4*)(ps + (size_t)ai * N_FEAT);
    float nrm = 0.f;
    #pragma unroll
    for (int t = 0; t < 4; ++t) {
        int v = lid + t * 32;                 // 0..127 float4s
        float4 f = __ldg(src + v);
        nrm += f.x * f.x + f.y * f.y + f.z * f.z + f.w * f.w;
        float hx = __bfloat162float(__float2bfloat16(f.x));
        float hy = __bfloat162float(__float2bfloat16(f.y));
        float hz = __bfloat162float(__float2bfloat16(f.z));
        float hw = __bfloat162float(__float2bfloat16(f.w));
        uint2 h = make_uint2(pkbf(hx, hy), pkbf(hz, hw));
        uint2 l = make_uint2(pkbf(f.x - hx, f.y - hy), pkbf(f.z - hz, f.w - hw));
        size_t o = (size_t)p * N_FEAT + v * 4;
        *(uint2*)((char*)g_Xh + o * 2) = h;
        *(uint2*)((char*)g_Xl + o * 2) = l;
    }
    #pragma unroll
    for (int o = 16; o; o >>= 1) nrm += __shfl_xor_sync(0xffffffffu, nrm, o);
    if (lid == 0) { g_invn[p] = 1.f / nrm; g_sidp[p] = sids[ai]; }
}

// ---------------- A_s = Y^T diag(c) Y -> bf16 hi/lo ----------------
__global__ __launch_bounds__(256) void k_computeA(const float* __restrict__ sp, int n_support) {
    int s = blockIdx.z;
    int i0 = blockIdx.y * 64, j0 = blockIdx.x * 64;
    __shared__ float Yi[16][64];
    __shared__ float Yj[16][64];
    int tid = threadIdx.x;
    int ty = tid >> 4, tx = tid & 15;
    float acc[4][4];
    #pragma unroll
    for (int a = 0; a < 4; ++a)
        #pragma unroll
        for (int b = 0; b < 4; ++b) acc[a][b] = 0.f;

    const float* Y = sp + (size_t)s * n_support * N_FEAT;
    const float* c = g_c + s * MAX_SUPPORT;

    for (int m0 = 0; m0 < n_support; m0 += 16) {
        #pragma unroll
        for (int it = 0; it < 4; ++it) {
            int idx = it * 256 + tid;
            int kk = idx >> 6, col = idx & 63;
            int m = m0 + kk;
            float yi = 0.f, yj = 0.f, cm = 0.f;
            if (m < n_support) {
                cm = c[m];
                yi = Y[(size_t)m * N_FEAT + i0 + col];
                yj = Y[(size_t)m * N_FEAT + j0 + col];
            }
            Yi[kk][col] = cm * yi;
            Yj[kk][col] = yj;
        }
        __syncthreads();
        #pragma unroll
        for (int kk = 0; kk < 16; ++kk) {
            float a[4], b[4];
            #pragma unroll
            for (int ii = 0; ii < 4; ++ii) a[ii] = Yi[kk][ty * 4 + ii];
            #pragma unroll
            for (int jj = 0; jj < 4; ++jj) b[jj] = Yj[kk][tx * 4 + jj];
            #pragma unroll
            for (int ii = 0; ii < 4; ++ii)
                #pragma unroll
                for (int jj = 0; jj < 4; ++jj) acc[ii][jj] += a[ii] * b[jj];
        }
        __syncthreads();
    }
    #pragma unroll
    for (int ii = 0; ii < 4; ++ii)
        #pragma unroll
        for (int jj = 0; jj < 4; ++jj) {
            int i = i0 + ty * 4 + ii;   // k index
            int j = j0 + tx * 4 + jj;   // n index
            float a = acc[ii][jj];
            __nv_bfloat16 h = __float2bfloat16(a);
            __nv_bfloat16 l = __float2bfloat16(a - __bfloat162float(h));
            size_t o = ((size_t)s * N_FEAT + i) * N_FEAT + j;
            g_Ah[o] = h;
            g_Al[o] = l;
        }
}

// ---------------- main MMA kernel ----------------
// SMEM buffer layout (bytes), double buffered:
#define XPIT     144                     // 72 bf16 row pitch (128 rows)
#define APIT     272                     // 136 bf16 row pitch (64 rows)
#define XH_OFF   0
#define XL_OFF   (128 * XPIT)            // 18432
#define AH_OFF   (2 * 128 * XPIT)        // 36864
#define AL_OFF   (AH_OFF + 64 * APIT)    // 54272
#define BUFSZ    (AL_OFF + 64 * APIT)    // 71680
#define ESM_OFF  (2 * BUFSZ)             // 143360
#define SMEM_DYN (ESM_OFF + 512)

__global__ __launch_bounds__(256, 1) void k_main_mma(float* __restrict__ out) {
    extern __shared__ char smem[];
    const uint32_t sb = smem_u32(smem);
    float* esm = (float*)(smem + ESM_OFF);

    const int tid = threadIdx.x, wid = tid >> 5, lid = tid & 31;
    const int s = blockIdx.y;
    const int off0 = g_off[s], off1 = g_off[s + 1];
    const int base = off0 + blockIdx.x * MT;
    if (base >= off1) return;
    const int valid = min(MT, off1 - base);

    if (tid < MT) esm[tid] = 0.f;

    const int mg = wid >> 2;     // 0..1 : 64 rows each
    const int ng = wid & 3;      // 0..3 : 32 cols each

    // per-lane ldmatrix address components
    const int xrow = (lid & 7) + ((lid >> 3) & 1) * 8;     // 0..15
    const int xkof = ((lid >> 4) & 1) * 8;
    const int akrow = (lid & 7) + ((lid >> 3) & 1) * 8;
    const int anof = ((lid >> 4) & 1) * 8;

    float er[4][2];
    #pragma unroll
    for (int a = 0; a < 4; ++a) { er[a][0] = 0.f; er[a][1] = 0.f; }

    for (int nc = 0; nc < N_FEAT / NC; ++nc) {
        float acc[4][4][4];
        #pragma unroll
        for (int a = 0; a < 4; ++a)
            #pragma unroll
            for (int b = 0; b < 4; ++b)
                #pragma unroll
                for (int q = 0; q < 4; ++q) acc[a][b][q] = 0.f;

        // issue loads for chunk kc into buffer kc&1
        auto issue = [&](int kc) {
            uint32_t bufb = sb + (kc & 1) * BUFSZ;
            // X: 2048 16B vectors (hi then lo)
            #pragma unroll
            for (int it = 0; it < 8; ++it) {
                int idx = it * 256 + tid;
                int sel = idx >> 10, e = idx & 1023;
                int r = e >> 3, v = e & 7;
                const __nv_bfloat16* g = sel ? g_Xl : g_Xh;
                const char* src = (const char*)(g + (size_t)(base + r) * N_FEAT + kc * KC + v * 8);
                cpasync16(bufb + (sel ? XL_OFF : XH_OFF) + r * XPIT + v * 16, src);
            }
            // A: 2048 16B vectors (hi then lo)
            #pragma unroll
            for (int it = 0; it < 8; ++it) {
                int idx = it * 256 + tid;
                int sel = idx >> 10, e = idx & 1023;
                int r = e >> 4, v = e & 15;
                const __nv_bfloat16* g = sel ? g_Al : g_Ah;
                const char* src = (const char*)(g + ((size_t)s * N_FEAT + kc * KC + r) * N_FEAT
                                                + nc * NC + v * 8);
                cpasync16(bufb + (sel ? AL_OFF : AH_OFF) + r * APIT + v * 16, src);
            }
        };

        issue(0); CP_COMMIT();

        for (int kc = 0; kc < N_FEAT / KC; ++kc) {
            if (kc + 1 < N_FEAT / KC) {
                issue(kc + 1); CP_COMMIT();
                asm volatile("cp.async.wait_group 1;" ::: "memory");
            } else {
                asm volatile("cp.async.wait_group 0;" ::: "memory");
            }
            __syncthreads();

            const uint32_t bufb = sb + (kc & 1) * BUFSZ;
            #pragma unroll
            for (int ks = 0; ks < KC / 16; ++ks) {
                // A fragments (hi, lo): 2 x ldmatrix.x4.trans each
                uint32_t bh[2][4], bl[2][4];
                #pragma unroll
                for (int t = 0; t < 2; ++t) {
                    uint32_t aa = bufb + AH_OFF + (ks * 16 + akrow) * APIT
                                + (ng * 32 + t * 16 + anof) * 2;
                    ldsm_x4t(bh[t], aa);
                    ldsm_x4t(bl[t], aa + (AL_OFF - AH_OFF));
                }
                // X hi fragments
                uint32_t xa[4][4];
                uint32_t xaddr[4];
                #pragma unroll
                for (int mt = 0; mt < 4; ++mt) {
                    xaddr[mt] = bufb + XH_OFF + (mg * 64 + mt * 16 + xrow) * XPIT
                              + (ks * 16 + xkof) * 2;
                    ldsm_x4(xa[mt], xaddr[mt]);
                }
                #pragma unroll
                for (int mt = 0; mt < 4; ++mt)
                    #pragma unroll
                    for (int nt = 0; nt < 4; ++nt) {
                        mma16816(acc[mt][nt], xa[mt], &bh[nt >> 1][(nt & 1) * 2]);
                        mma16816(acc[mt][nt], xa[mt], &bl[nt >> 1][(nt & 1) * 2]);
                    }
                // X lo fragments (reuse regs)
                #pragma unroll
                for (int mt = 0; mt < 4; ++mt)
                    ldsm_x4(xa[mt], xaddr[mt] + (XL_OFF - XH_OFF));
                #pragma unroll
                for (int mt = 0; mt < 4; ++mt)
                    #pragma unroll
                    for (int nt = 0; nt < 4; ++nt)
                        mma16816(acc[mt][nt], xa[mt], &bh[nt >> 1][(nt & 1) * 2]);
            }
            __syncthreads();
        }

        // fold D .* x into per-row partials
        #pragma unroll
        for (int mt = 0; mt < 4; ++mt) {
            int r0 = base + mg * 64 + mt * 16 + (lid >> 2);
            #pragma unroll
            for (int nt = 0; nt < 4; ++nt) {
                int j = nc * NC + ng * 32 + nt * 8 + (lid & 3) * 2;
                size_t o0 = (size_t)r0 * N_FEAT + j;
                size_t o1 = o0 + 8 * N_FEAT;
                float2 h0 = __bfloat1622float2(*(const __nv_bfloat162*)((const char*)g_Xh + o0 * 2));
                float2 l0 = __bfloat1622float2(*(const __nv_bfloat162*)((const char*)g_Xl + o0 * 2));
                float2 h1 = __bfloat1622float2(*(const __nv_bfloat162*)((const char*)g_Xh + o1 * 2));
                float2 l1 = __bfloat1622float2(*(const __nv_bfloat162*)((const char*)g_Xl + o1 * 2));
                er[mt][0] += acc[mt][nt][0] * (h0.x + l0.x) + acc[mt][nt][1] * (h0.y + l0.y);
                er[mt][1] += acc[mt][nt][2] * (h1.x + l1.x) + acc[mt][nt][3] * (h1.y + l1.y);
            }
        }
    }

    // reduce quad lanes (same row, different col pairs), then SMEM atomic
    #pragma unroll
    for (int mt = 0; mt < 4; ++mt)
        #pragma unroll
        for (int hh = 0; hh < 2; ++hh) {
            float v = er[mt][hh];
            v += __shfl_xor_sync(0xffffffffu, v, 1);
            v += __shfl_xor_sync(0xffffffffu, v, 2);
            if ((lid & 3) == 0)
                atomicAdd(&esm[mg * 64 + mt * 16 + (lid >> 2) + hh * 8], v);
        }
    __syncthreads();

    if (tid < valid) {
        int p = base + tid;
        atomicAdd(&out[g_sidp[p]], esm[tid] * g_invn[p]);
    }
}

// ---------------- launch ----------------
extern "C" void kernel_launch(void* const* d_in, const int* in_sizes, int n_in,
                              void* d_out, int out_size) {
    const float* ps   = (const float*)d_in[0];
    const float* sp   = (const float*)d_in[1];
    const float* w    = (const float*)d_in[2];
    const int*   spec = (const int*)d_in[3];
    const int*   sids = (const int*)d_in[4];
    float* out = (float*)d_out;

    int n_atoms   = in_sizes[3];
    int n_support = in_sizes[2] / N_SPECIES;

    cudaFuncSetAttribute(k_main_mma, cudaFuncAttributeMaxDynamicSharedMemorySize, SMEM_DYN);

    int init_n = out_size > N_SPECIES ? out_size : N_SPECIES;
    k_init<<<(init_n + 255) / 256, 256>>>(out, out_size);
    k_prep_c<<<N_SPECIES * n_support, 128>>>(sp, w, n_support);
    k_count<<<(n_atoms + 255) / 256, 256>>>(spec, n_atoms);
    k_off<<<1, 32>>>();
    k_scatter<<<(n_atoms + 255) / 256, 256>>>(spec, n_atoms);
    k_prepX<<<(n_atoms + 7) / 8, 256>>>(ps, sids, n_atoms);
    k_computeA<<<dim3(N_FEAT / 64, N_FEAT / 64, N_SPECIES), 256>>>(sp, n_support);

    dim3 grid((n_atoms + MT - 1) / MT, N_SPECIES);
    k_main_mma<<<grid, 256, SMEM_DYN>>>(out);
}

// round 4
// speedup vs baseline: 3.4847x; 1.3841x over previous
#include <cuda_runtime.h>
#include <cuda_bf16.h>
#include <stdint.h>

// SparseGapPerSpecies via quadratic form + warp bf16 MMA, symmetry-reduced:
//   A_s = Y_s^T diag(w/|y|^2) Y_s  (symmetric) -> bf16 hi+lo
//   x'Ax = xh'A(xh+2xl) + O(2^-16)  => Q = Xh*(Ah+Al): only 2 GEMM terms
//   e_atom = rowdot(Q, xh+2xl)/|x|^2 ; energy = segment_sum
// No tcgen05/TMA: harness ptxas targets plain sm_103.

#define N_SPECIES   4
#define N_FEAT      512
#define MAX_ATOMS   100352
#define MAX_SUPPORT 1024
#define MT          128
#define NC          128
#define KC          64

__device__ __nv_bfloat16 g_Ah[N_SPECIES * N_FEAT * N_FEAT];  // [s][k][n]
__device__ __nv_bfloat16 g_Al[N_SPECIES * N_FEAT * N_FEAT];
__device__ __nv_bfloat16 g_Xh[(size_t)MAX_ATOMS * N_FEAT];   // sorted by species
__device__ __nv_bfloat16 g_Xl[(size_t)MAX_ATOMS * N_FEAT];
__device__ float g_invn[MAX_ATOMS];
__device__ int   g_sidp[MAX_ATOMS];
__device__ float g_c[N_SPECIES * MAX_SUPPORT];
__device__ int   g_cnt[N_SPECIES];        // zero-init; k_off resets after use
__device__ int   g_off[N_SPECIES + 1];
__device__ int   g_cur[N_SPECIES];

// ---------------- PTX helpers ----------------
__device__ __forceinline__ uint32_t smem_u32(const void* p) {
    uint32_t a;
    asm("{ .reg .u64 t; cvta.to.shared.u64 t, %1; cvt.u32.u64 %0, t; }" : "=r"(a) : "l"(p));
    return a;
}
__device__ __forceinline__ void cpasync16(uint32_t dst, const void* src) {
    asm volatile("cp.async.cg.shared.global [%0], [%1], 16;" :: "r"(dst), "l"(src) : "memory");
}
#define CP_COMMIT() asm volatile("cp.async.commit_group;" ::: "memory")

__device__ __forceinline__ void ldsm_x4(uint32_t* r, uint32_t a) {
    asm volatile("ldmatrix.sync.aligned.m8n8.x4.shared.b16 {%0,%1,%2,%3}, [%4];"
                 : "=r"(r[0]), "=r"(r[1]), "=r"(r[2]), "=r"(r[3]) : "r"(a));
}
__device__ __forceinline__ void ldsm_x4t(uint32_t* r, uint32_t a) {
    asm volatile("ldmatrix.sync.aligned.m8n8.x4.trans.shared.b16 {%0,%1,%2,%3}, [%4];"
                 : "=r"(r[0]), "=r"(r[1]), "=r"(r[2]), "=r"(r[3]) : "r"(a));
}
__device__ __forceinline__ void mma16816(float* c, const uint32_t* a, const uint32_t* b) {
    asm volatile("mma.sync.aligned.m16n8k16.row.col.f32.bf16.bf16.f32 "
                 "{%0,%1,%2,%3},{%4,%5,%6,%7},{%8,%9},{%0,%1,%2,%3};"
                 : "+f"(c[0]), "+f"(c[1]), "+f"(c[2]), "+f"(c[3])
                 : "r"(a[0]), "r"(a[1]), "r"(a[2]), "r"(a[3]), "r"(b[0]), "r"(b[1]));
}
__device__ __forceinline__ uint32_t pkbf(float a, float b) {
    __nv_bfloat162 t = __floats2bfloat162_rn(a, b);
    return *(uint32_t*)&t;
}

// ---------------- 1: per-support scale c = w/|y|^2 ----------------
__global__ void k_prep_c(const float* __restrict__ sp, const float* __restrict__ w,
                         int n_support) {
    int b = blockIdx.x;
    int s = b / n_support, m = b % n_support;
    const float* y = sp + (size_t)(s * n_support + m) * N_FEAT;
    float acc = 0.f;
    for (int i = threadIdx.x; i < N_FEAT; i += 128) { float v = y[i]; acc += v * v; }
    #pragma unroll
    for (int o = 16; o; o >>= 1) acc += __shfl_xor_sync(0xffffffffu, acc, o);
    __shared__ float r[4];
    if ((threadIdx.x & 31) == 0) r[threadIdx.x >> 5] = acc;
    __syncthreads();
    if (threadIdx.x == 0)
        g_c[s * MAX_SUPPORT + m] = w[s * n_support + m] / (r[0] + r[1] + r[2] + r[3]);
}

// ---------------- 2: count species + zero output ----------------
__global__ void k_countz(const int* __restrict__ spc, int n, float* out, int n_out) {
    int i = blockIdx.x * 256 + threadIdx.x;
    if (i < n) atomicAdd(&g_cnt[spc[i]], 1);
    if (i < n_out) out[i] = 0.f;
}

// ---------------- 3: offsets (+ reset counters for next replay) ----------------
__global__ void k_off() {
    if (threadIdx.x == 0) {
        int acc = 0;
        for (int s = 0; s < N_SPECIES; ++s) {
            g_off[s] = acc; g_cur[s] = acc; acc += g_cnt[s]; g_cnt[s] = 0;
        }
        g_off[N_SPECIES] = acc;
    }
}

// ---------------- 4: A_s = Y^T diag(c) Y -> bf16 hi/lo (upper-tri + mirror) ----------------
__global__ __launch_bounds__(256) void k_computeA(const float* __restrict__ sp, int n_support) {
    int s = blockIdx.z;
    // map blockIdx.x in [0,36) to upper-tri pair (bi<=bj) of 8x8 blocks
    int t = blockIdx.x;
    int bi = 0;
    { int rem = t; int rowlen = 8;
      while (rem >= rowlen) { rem -= rowlen; rowlen--; bi++; }
      t = rem; }
    int bj = bi + t;
    int i0 = bi * 64, j0 = bj * 64;

    __shared__ float Yi[16][64];
    __shared__ float Yj[16][64];
    int tid = threadIdx.x;
    int ty = tid >> 4, tx = tid & 15;
    float acc[4][4];
    #pragma unroll
    for (int a = 0; a < 4; ++a)
        #pragma unroll
        for (int b = 0; b < 4; ++b) acc[a][b] = 0.f;

    const float* Y = sp + (size_t)s * n_support * N_FEAT;
    const float* c = g_c + s * MAX_SUPPORT;

    for (int m0 = 0; m0 < n_support; m0 += 16) {
        #pragma unroll
        for (int it = 0; it < 4; ++it) {
            int idx = it * 256 + tid;
            int kk = idx >> 6, col = idx & 63;
            int m = m0 + kk;
            float yi = 0.f, yj = 0.f, cm = 0.f;
            if (m < n_support) {
                cm = c[m];
                yi = Y[(size_t)m * N_FEAT + i0 + col];
                yj = Y[(size_t)m * N_FEAT + j0 + col];
            }
            Yi[kk][col] = cm * yi;
            Yj[kk][col] = yj;
        }
        __syncthreads();
        #pragma unroll
        for (int kk = 0; kk < 16; ++kk) {
            float a[4], b[4];
            #pragma unroll
            for (int ii = 0; ii < 4; ++ii) a[ii] = Yi[kk][ty * 4 + ii];
            #pragma unroll
            for (int jj = 0; jj < 4; ++jj) b[jj] = Yj[kk][tx * 4 + jj];
            #pragma unroll
            for (int ii = 0; ii < 4; ++ii)
                #pragma unroll
                for (int jj = 0; jj < 4; ++jj) acc[ii][jj] += a[ii] * b[jj];
        }
        __syncthreads();
    }
    #pragma unroll
    for (int ii = 0; ii < 4; ++ii)
        #pragma unroll
        for (int jj = 0; jj < 4; ++jj) {
            int i = i0 + ty * 4 + ii;
            int j = j0 + tx * 4 + jj;
            float a = acc[ii][jj];
            __nv_bfloat16 h = __float2bfloat16(a);
            __nv_bfloat16 l = __float2bfloat16(a - __bfloat162float(h));
            size_t o = ((size_t)s * N_FEAT + i) * N_FEAT + j;
            g_Ah[o] = h; g_Al[o] = l;
            if (bi != bj) {
                size_t om = ((size_t)s * N_FEAT + j) * N_FEAT + i;
                g_Ah[om] = h; g_Al[om] = l;
            }
        }
}

// ---------------- 5: scatter + bf16 split + norms (warp per atom) ----------------
__global__ __launch_bounds__(256) void k_scatterX(const float* __restrict__ ps,
                                                  const int* __restrict__ spc,
                                                  const int* __restrict__ sids, int n) {
    int wid = threadIdx.x >> 5, lid = threadIdx.x & 31;
    int i = blockIdx.x * 8 + wid;
    if (i >= n) return;
    int p;
    if (lid == 0) p = atomicAdd(&g_cur[spc[i]], 1);
    p = __shfl_sync(0xffffffffu, p, 0);

    const float4* src = (const float4*)(ps + (size_t)i * N_FEAT);
    float nrm = 0.f;
    #pragma unroll
    for (int t = 0; t < 4; ++t) {
        int v = lid + t * 32;
        float4 f = __ldg(src + v);
        nrm += f.x * f.x + f.y * f.y + f.z * f.z + f.w * f.w;
        float hx = __bfloat162float(__float2bfloat16(f.x));
        float hy = __bfloat162float(__float2bfloat16(f.y));
        float hz = __bfloat162float(__float2bfloat16(f.z));
        float hw = __bfloat162float(__float2bfloat16(f.w));
        uint2 h = make_uint2(pkbf(hx, hy), pkbf(hz, hw));
        uint2 l = make_uint2(pkbf(f.x - hx, f.y - hy), pkbf(f.z - hz, f.w - hw));
        size_t o = (size_t)p * N_FEAT + v * 4;
        *(uint2*)((char*)g_Xh + o * 2) = h;
        *(uint2*)((char*)g_Xl + o * 2) = l;
    }
    #pragma unroll
    for (int o = 16; o; o >>= 1) nrm += __shfl_xor_sync(0xffffffffu, nrm, o);
    if (lid == 0) { g_invn[p] = 1.f / nrm; g_sidp[p] = sids[i]; }
}

// ---------------- 6: main MMA kernel ----------------
#define XPIT     144                     // 64 bf16 + 8 pad
#define APIT     272                     // 128 bf16 + 8 pad
#define XH_OFF   0
#define AH_OFF   (128 * XPIT)            // 18432
#define AL_OFF   (AH_OFF + 64 * APIT)    // 35840
#define BUFSZ    (AL_OFF + 64 * APIT)    // 53248
#define ESM_OFF  (2 * BUFSZ)             // 106496
#define SMEM_DYN (ESM_OFF + 512)

__global__ __launch_bounds__(256, 2) void k_main_mma(float* __restrict__ out) {
    extern __shared__ char smem[];
    const uint32_t sb = smem_u32(smem);
    float* esm = (float*)(smem + ESM_OFF);

    const int tid = threadIdx.x, wid = tid >> 5, lid = tid & 31;
    const int s = blockIdx.y;
    const int off0 = g_off[s], off1 = g_off[s + 1];
    const int base = off0 + blockIdx.x * MT;
    if (base >= off1) return;
    const int valid = min(MT, off1 - base);

    if (tid < MT) esm[tid] = 0.f;

    const int mg = wid >> 2;     // 0..1 : 64 rows each
    const int ng = wid & 3;      // 0..3 : 32 cols each

    const int xrow = (lid & 7) + ((lid >> 3) & 1) * 8;
    const int xkof = ((lid >> 4) & 1) * 8;
    const int akrow = (lid & 7) + ((lid >> 3) & 1) * 8;
    const int anof = ((lid >> 4) & 1) * 8;

    for (int nc = 0; nc < N_FEAT / NC; ++nc) {
        float acc[4][4][4];
        #pragma unroll
        for (int a = 0; a < 4; ++a)
            #pragma unroll
            for (int b = 0; b < 4; ++b)
                #pragma unroll
                for (int q = 0; q < 4; ++q) acc[a][b][q] = 0.f;

        auto issue = [&](int kc) {
            uint32_t bufb = sb + (kc & 1) * BUFSZ;
            // X hi: 1024 16B vectors
            #pragma unroll
            for (int it = 0; it < 4; ++it) {
                int idx = it * 256 + tid;
                int r = idx >> 3, v = idx & 7;
                const char* src = (const char*)(g_Xh + (size_t)(base + r) * N_FEAT
                                                + kc * KC + v * 8);
                cpasync16(bufb + XH_OFF + r * XPIT + v * 16, src);
            }
            // A hi+lo: 2048 16B vectors
            #pragma unroll
            for (int it = 0; it < 8; ++it) {
                int idx = it * 256 + tid;
                int sel = idx >> 10, e = idx & 1023;
                int r = e >> 4, v = e & 15;
                const __nv_bfloat16* g = sel ? g_Al : g_Ah;
                const char* src = (const char*)(g + ((size_t)s * N_FEAT + kc * KC + r) * N_FEAT
                                                + nc * NC + v * 8);
                cpasync16(bufb + (sel ? AL_OFF : AH_OFF) + r * APIT + v * 16, src);
            }
        };

        issue(0); CP_COMMIT();

        for (int kc = 0; kc < N_FEAT / KC; ++kc) {
            if (kc + 1 < N_FEAT / KC) {
                issue(kc + 1); CP_COMMIT();
                asm volatile("cp.async.wait_group 1;" ::: "memory");
            } else {
                asm volatile("cp.async.wait_group 0;" ::: "memory");
            }
            __syncthreads();

            const uint32_t bufb = sb + (kc & 1) * BUFSZ;
            #pragma unroll
            for (int ks = 0; ks < KC / 16; ++ks) {
                uint32_t bh[2][4], bl[2][4];
                #pragma unroll
                for (int t = 0; t < 2; ++t) {
                    uint32_t aa = bufb + AH_OFF + (ks * 16 + akrow) * APIT
                                + (ng * 32 + t * 16 + anof) * 2;
                    ldsm_x4t(bh[t], aa);
                    ldsm_x4t(bl[t], aa + (AL_OFF - AH_OFF));
                }
                uint32_t xa[4][4];
                #pragma unroll
                for (int mt = 0; mt < 4; ++mt) {
                    uint32_t xaddr = bufb + XH_OFF + (mg * 64 + mt * 16 + xrow) * XPIT
                                   + (ks * 16 + xkof) * 2;
                    ldsm_x4(xa[mt], xaddr);
                }
                #pragma unroll
                for (int mt = 0; mt < 4; ++mt)
                    #pragma unroll
                    for (int nt = 0; nt < 4; ++nt) {
                        mma16816(acc[mt][nt], xa[mt], &bh[nt >> 1][(nt & 1) * 2]);
                        mma16816(acc[mt][nt], xa[mt], &bl[nt >> 1][(nt & 1) * 2]);
                    }
            }
            __syncthreads();
        }

        // epilogue: e += Q .* (xh + 2*xl)
        float er[4][2];
        #pragma unroll
        for (int a = 0; a < 4; ++a) { er[a][0] = 0.f; er[a][1] = 0.f; }
        #pragma unroll
        for (int mt = 0; mt < 4; ++mt) {
            int r0 = base + mg * 64 + mt * 16 + (lid >> 2);
            #pragma unroll
            for (int nt = 0; nt < 4; ++nt) {
                int j = nc * NC + ng * 32 + nt * 8 + (lid & 3) * 2;
                size_t o0 = (size_t)r0 * N_FEAT + j;
                size_t o1 = o0 + 8 * N_FEAT;
                float2 h0 = __bfloat1622float2(*(const __nv_bfloat162*)((const char*)g_Xh + o0 * 2));
                float2 l0 = __bfloat1622float2(*(const __nv_bfloat162*)((const char*)g_Xl + o0 * 2));
                float2 h1 = __bfloat1622float2(*(const __nv_bfloat162*)((const char*)g_Xh + o1 * 2));
                float2 l1 = __bfloat1622float2(*(const __nv_bfloat162*)((const char*)g_Xl + o1 * 2));
                er[mt][0] += acc[mt][nt][0] * (h0.x + 2.f * l0.x)
                           + acc[mt][nt][1] * (h0.y + 2.f * l0.y);
                er[mt][1] += acc[mt][nt][2] * (h1.x + 2.f * l1.x)
                           + acc[mt][nt][3] * (h1.y + 2.f * l1.y);
            }
        }
        #pragma unroll
        for (int mt = 0; mt < 4; ++mt)
            #pragma unroll
            for (int hh = 0; hh < 2; ++hh) {
                float v = er[mt][hh];
                v += __shfl_xor_sync(0xffffffffu, v, 1);
                v += __shfl_xor_sync(0xffffffffu, v, 2);
                if ((lid & 3) == 0)
                    atomicAdd(&esm[mg * 64 + mt * 16 + (lid >> 2) + hh * 8], v);
            }
    }
    __syncthreads();

    if (tid < valid) {
        int p = base + tid;
        atomicAdd(&out[g_sidp[p]], esm[tid] * g_invn[p]);
    }
}

// ---------------- launch ----------------
extern "C" void kernel_launch(void* const* d_in, const int* in_sizes, int n_in,
                              void* d_out, int out_size) {
    const float* ps   = (const float*)d_in[0];
    const float* sp   = (const float*)d_in[1];
    const float* w    = (const float*)d_in[2];
    const int*   spec = (const int*)d_in[3];
    const int*   sids = (const int*)d_in[4];
    float* out = (float*)d_out;

    int n_atoms   = in_sizes[3];
    int n_support = in_sizes[2] / N_SPECIES;

    cudaFuncSetAttribute(k_main_mma, cudaFuncAttributeMaxDynamicSharedMemorySize, SMEM_DYN);

    k_prep_c<<<N_SPECIES * n_support, 128>>>(sp, w, n_support);
    k_countz<<<(n_atoms + 255) / 256, 256>>>(spec, n_atoms, out, out_size);
    k_off<<<1, 32>>>();
    k_computeA<<<dim3(36, 1, N_SPECIES), 256>>>(sp, n_support);
    k_scatterX<<<(n_atoms + 7) / 8, 256>>>(ps, spec, sids, n_atoms);

    dim3 grid((n_atoms + MT - 1) / MT, N_SPECIES);
    k_main_mma<<<grid, 256, SMEM_DYN>>>(out);
}

// round 5
// speedup vs baseline: 3.5513x; 1.0191x over previous
#include <cuda_runtime.h>
#include <cuda_bf16.h>
#include <stdint.h>

// SparseGapPerSpecies: quadratic form + warp bf16 MMA, symmetry-reduced.
//   A_s = Y_s^T diag(w/|y|^2) Y_s (symmetric) -> bf16 hi+lo
//   x'Ax = xh'A(xh+2xl) + O(2^-16)  => Q = Xh*(Ah+Al): 2 GEMM terms
//   e_atom = rowdot(Q, xh + 2xl)/|x|^2 ; energy = segment_sum
// Launch plan (ncu profiles launch #4): fuse1, off, fuse2, MAIN.

#define N_SPECIES   4
#define N_FEAT      512
#define MAX_ATOMS   100352
#define MAX_SUPPORT 1024
#define MT          128
#define NC          128
#define KC          64

__device__ __nv_bfloat16 g_Ah[N_SPECIES * N_FEAT * N_FEAT];  // [s][k][n]
__device__ __nv_bfloat16 g_Al[N_SPECIES * N_FEAT * N_FEAT];
__device__ __nv_bfloat16 g_Xh[(size_t)MAX_ATOMS * N_FEAT];   // sorted by species
__device__ __nv_bfloat16 g_Xl[(size_t)MAX_ATOMS * N_FEAT];   // holds 2*xl
__device__ float g_invn[MAX_ATOMS];
__device__ int   g_sidp[MAX_ATOMS];
__device__ float g_c[N_SPECIES * MAX_SUPPORT];
__device__ int   g_cnt[N_SPECIES];        // zero-init; k_off resets after use
__device__ int   g_off[N_SPECIES + 1];
__device__ int   g_cur[N_SPECIES];

// ---------------- PTX helpers ----------------
__device__ __forceinline__ uint32_t smem_u32(const void* p) {
    uint32_t a;
    asm("{ .reg .u64 t; cvta.to.shared.u64 t, %1; cvt.u32.u64 %0, t; }" : "=r"(a) : "l"(p));
    return a;
}
__device__ __forceinline__ void cpasync16(uint32_t dst, const void* src) {
    asm volatile("cp.async.cg.shared.global [%0], [%1], 16;" :: "r"(dst), "l"(src) : "memory");
}
#define CP_COMMIT() asm volatile("cp.async.commit_group;" ::: "memory")

__device__ __forceinline__ void ldsm_x4(uint32_t* r, uint32_t a) {
    asm volatile("ldmatrix.sync.aligned.m8n8.x4.shared.b16 {%0,%1,%2,%3}, [%4];"
                 : "=r"(r[0]), "=r"(r[1]), "=r"(r[2]), "=r"(r[3]) : "r"(a));
}
__device__ __forceinline__ void ldsm_x4t(uint32_t* r, uint32_t a) {
    asm volatile("ldmatrix.sync.aligned.m8n8.x4.trans.shared.b16 {%0,%1,%2,%3}, [%4];"
                 : "=r"(r[0]), "=r"(r[1]), "=r"(r[2]), "=r"(r[3]) : "r"(a));
}
__device__ __forceinline__ void mma16816(float* c, const uint32_t* a, const uint32_t* b) {
    asm volatile("mma.sync.aligned.m16n8k16.row.col.f32.bf16.bf16.f32 "
                 "{%0,%1,%2,%3},{%4,%5,%6,%7},{%8,%9},{%0,%1,%2,%3};"
                 : "+f"(c[0]), "+f"(c[1]), "+f"(c[2]), "+f"(c[3])
                 : "r"(a[0]), "r"(a[1]), "r"(a[2]), "r"(a[3]), "r"(b[0]), "r"(b[1]));
}
__device__ __forceinline__ uint32_t pkbf(float a, float b) {
    __nv_bfloat162 t = __floats2bfloat162_rn(a, b);
    return *(uint32_t*)&t;
}

// ---------------- launch 1: prep_c (4 pts/block) || countz ----------------
__global__ __launch_bounds__(512) void k_fuse1(const float* __restrict__ sp,
                                               const float* __restrict__ w,
                                               int n_support,
                                               const int* __restrict__ spc, int n,
                                               float* out, int n_out, int pb) {
    int bx = blockIdx.x;
    if (bx < pb) {
        // prep_c: 4 support points per block, 128 threads each
        __shared__ float r[4][4];
        int g = threadIdx.x >> 7, st = threadIdx.x & 127;
        int pt = bx * 4 + g;
        int total = N_SPECIES * n_support;
        float acc = 0.f;
        if (pt < total) {
            const float* y = sp + (size_t)pt * N_FEAT;
            #pragma unroll
            for (int t = 0; t < 4; ++t) { float v = y[st + t * 128]; acc += v * v; }
        }
        #pragma unroll
        for (int o = 16; o; o >>= 1) acc += __shfl_xor_sync(0xffffffffu, acc, o);
        if ((st & 31) == 0) r[g][st >> 5] = acc;
        __syncthreads();
        if (st == 0 && pt < total) {
            int s = pt / n_support, m = pt % n_support;
            g_c[s * MAX_SUPPORT + m] = w[pt] / (r[g][0] + r[g][1] + r[g][2] + r[g][3]);
        }
    } else {
        int i = (bx - pb) * 512 + threadIdx.x;
        if (i < n) atomicAdd(&g_cnt[spc[i]], 1);
        if (i < n_out) out[i] = 0.f;
    }
}

// ---------------- launch 2: offsets (+ reset counters for replay) ----------------
__global__ void k_off() {
    if (threadIdx.x == 0) {
        int acc = 0;
        for (int s = 0; s < N_SPECIES; ++s) {
            g_off[s] = acc; g_cur[s] = acc; acc += g_cnt[s]; g_cnt[s] = 0;
        }
        g_off[N_SPECIES] = acc;
    }
}

// ---------------- launch 3: computeA (144 blocks) || scatterX ----------------
__global__ __launch_bounds__(512) void k_fuse2(const float* __restrict__ sp, int n_support,
                                               const float* __restrict__ ps,
                                               const int* __restrict__ spc,
                                               const int* __restrict__ sids, int n) {
    int bx = blockIdx.x;
    if (bx < 36 * N_SPECIES) {
        // ---- computeA: A = Y' diag(c) Y, upper-tri 64x64 tile + mirror ----
        __shared__ float Yi[16][64];
        __shared__ float Yj[16][64];
        int s = bx / 36;
        int t = bx % 36;
        int bi = 0;
        { int rowlen = 8; while (t >= rowlen) { t -= rowlen; rowlen--; bi++; } }
        int bj = bi + t;
        int i0 = bi * 64, j0 = bj * 64;

        int tid = threadIdx.x;
        int ty = tid >> 4, tx = tid & 15;     // 32 x 16 threads, 2x4 acc
        float acc[2][4];
        #pragma unroll
        for (int a = 0; a < 2; ++a)
            #pragma unroll
            for (int b = 0; b < 4; ++b) acc[a][b] = 0.f;

        const float* Y = sp + (size_t)s * n_support * N_FEAT;
        const float* c = g_c + s * MAX_SUPPORT;

        for (int m0 = 0; m0 < n_support; m0 += 16) {
            #pragma unroll
            for (int it = 0; it < 2; ++it) {
                int idx = it * 512 + tid;
                int kk = idx >> 6, col = idx & 63;
                int m = m0 + kk;
                float yi = 0.f, yj = 0.f, cm = 0.f;
                if (m < n_support) {
                    cm = c[m];
                    yi = Y[(size_t)m * N_FEAT + i0 + col];
                    yj = Y[(size_t)m * N_FEAT + j0 + col];
                }
                Yi[kk][col] = cm * yi;
                Yj[kk][col] = yj;
            }
            __syncthreads();
            #pragma unroll
            for (int kk = 0; kk < 16; ++kk) {
                float a0 = Yi[kk][ty * 2], a1 = Yi[kk][ty * 2 + 1];
                float b[4];
                #pragma unroll
                for (int jj = 0; jj < 4; ++jj) b[jj] = Yj[kk][tx * 4 + jj];
                #pragma unroll
                for (int jj = 0; jj < 4; ++jj) { acc[0][jj] += a0 * b[jj]; acc[1][jj] += a1 * b[jj]; }
            }
            __syncthreads();
        }
        #pragma unroll
        for (int ii = 0; ii < 2; ++ii)
            #pragma unroll
            for (int jj = 0; jj < 4; ++jj) {
                int i = i0 + ty * 2 + ii;
                int j = j0 + tx * 4 + jj;
                float a = acc[ii][jj];
                __nv_bfloat16 h = __float2bfloat16(a);
                __nv_bfloat16 l = __float2bfloat16(a - __bfloat162float(h));
                size_t o = ((size_t)s * N_FEAT + i) * N_FEAT + j;
                g_Ah[o] = h; g_Al[o] = l;
                if (bi != bj) {
                    size_t om = ((size_t)s * N_FEAT + j) * N_FEAT + i;
                    g_Ah[om] = h; g_Al[om] = l;
                }
            }
    } else {
        // ---- scatterX: warp per atom; store xh and 2*xl; 1/|x|^2; sid ----
        int wid = threadIdx.x >> 5, lid = threadIdx.x & 31;
        int i = (bx - 36 * N_SPECIES) * 16 + wid;
        if (i >= n) return;
        int p;
        if (lid == 0) p = atomicAdd(&g_cur[spc[i]], 1);
        p = __shfl_sync(0xffffffffu, p, 0);

        const float4* src = (const float4*)(ps + (size_t)i * N_FEAT);
        float nrm = 0.f;
        #pragma unroll
        for (int t = 0; t < 4; ++t) {
            int v = lid + t * 32;
            float4 f = __ldg(src + v);
            nrm += f.x * f.x + f.y * f.y + f.z * f.z + f.w * f.w;
            float hx = __bfloat162float(__float2bfloat16(f.x));
            float hy = __bfloat162float(__float2bfloat16(f.y));
            float hz = __bfloat162float(__float2bfloat16(f.z));
            float hw = __bfloat162float(__float2bfloat16(f.w));
            uint2 h = make_uint2(pkbf(hx, hy), pkbf(hz, hw));
            uint2 l = make_uint2(pkbf(2.f * (f.x - hx), 2.f * (f.y - hy)),
                                 pkbf(2.f * (f.z - hz), 2.f * (f.w - hw)));
            size_t o = (size_t)p * N_FEAT + v * 4;
            *(uint2*)((char*)g_Xh + o * 2) = h;
            *(uint2*)((char*)g_Xl + o * 2) = l;
        }
        #pragma unroll
        for (int o = 16; o; o >>= 1) nrm += __shfl_xor_sync(0xffffffffu, nrm, o);
        if (lid == 0) { g_invn[p] = 1.f / nrm; g_sidp[p] = sids[i]; }
    }
}

// ---------------- launch 4: main MMA kernel ----------------
#define XPIT     144                     // 64 bf16 + 8 pad
#define APIT     272                     // 128 bf16 + 8 pad
#define XH_OFF   0
#define AH_OFF   (128 * XPIT)            // 18432
#define AL_OFF   (AH_OFF + 64 * APIT)    // 35840
#define BUFSZ    (AL_OFF + 64 * APIT)    // 53248
#define ESM_OFF  (2 * BUFSZ)             // 106496
#define SMEM_DYN (ESM_OFF + 512)

__global__ __launch_bounds__(256, 2) void k_main_mma(float* __restrict__ out) {
    extern __shared__ char smem[];
    const uint32_t sb = smem_u32(smem);
    float* esm = (float*)(smem + ESM_OFF);

    const int tid = threadIdx.x, wid = tid >> 5, lid = tid & 31;
    const int s = blockIdx.y;
    const int off0 = g_off[s], off1 = g_off[s + 1];
    const int base = off0 + blockIdx.x * MT;
    if (base >= off1) return;
    const int valid = min(MT, off1 - base);

    if (tid < MT) esm[tid] = 0.f;

    const int mg = wid >> 2;     // 0..1 : 64 rows each
    const int ng = wid & 3;      // 0..3 : 32 cols each

    const int xrow = (lid & 7) + ((lid >> 3) & 1) * 8;
    const int xkof = ((lid >> 4) & 1) * 8;
    const int akrow = (lid & 7) + ((lid >> 3) & 1) * 8;
    const int anof = ((lid >> 4) & 1) * 8;

    float er[4][2];
    #pragma unroll
    for (int a = 0; a < 4; ++a) { er[a][0] = 0.f; er[a][1] = 0.f; }

    for (int nc = 0; nc < N_FEAT / NC; ++nc) {
        float acc[4][4][4];
        #pragma unroll
        for (int a = 0; a < 4; ++a)
            #pragma unroll
            for (int b = 0; b < 4; ++b)
                #pragma unroll
                for (int q = 0; q < 4; ++q) acc[a][b][q] = 0.f;

        auto issue = [&](int kc) {
            uint32_t bufb = sb + (kc & 1) * BUFSZ;
            #pragma unroll
            for (int it = 0; it < 4; ++it) {
                int idx = it * 256 + tid;
                int r = idx >> 3, v = idx & 7;
                const char* src = (const char*)(g_Xh + (size_t)(base + r) * N_FEAT
                                                + kc * KC + v * 8);
                cpasync16(bufb + XH_OFF + r * XPIT + v * 16, src);
            }
            #pragma unroll
            for (int it = 0; it < 8; ++it) {
                int idx = it * 256 + tid;
                int sel = idx >> 10, e = idx & 1023;
                int r = e >> 4, v = e & 15;
                const __nv_bfloat16* g = sel ? g_Al : g_Ah;
                const char* src = (const char*)(g + ((size_t)s * N_FEAT + kc * KC + r) * N_FEAT
                                                + nc * NC + v * 8);
                cpasync16(bufb + (sel ? AL_OFF : AH_OFF) + r * APIT + v * 16, src);
            }
        };

        issue(0); CP_COMMIT();

        for (int kc = 0; kc < N_FEAT / KC; ++kc) {
            if (kc + 1 < N_FEAT / KC) {
                issue(kc + 1); CP_COMMIT();
                asm volatile("cp.async.wait_group 1;" ::: "memory");
            } else {
                asm volatile("cp.async.wait_group 0;" ::: "memory");
            }
            __syncthreads();

            const uint32_t bufb = sb + (kc & 1) * BUFSZ;
            #pragma unroll
            for (int ks = 0; ks < KC / 16; ++ks) {
                uint32_t bh[2][4], bl[2][4];
                #pragma unroll
                for (int t = 0; t < 2; ++t) {
                    uint32_t aa = bufb + AH_OFF + (ks * 16 + akrow) * APIT
                                + (ng * 32 + t * 16 + anof) * 2;
                    ldsm_x4t(bh[t], aa);
                    ldsm_x4t(bl[t], aa + (AL_OFF - AH_OFF));
                }
                uint32_t xa[4][4];
                #pragma unroll
                for (int mt = 0; mt < 4; ++mt) {
                    uint32_t xaddr = bufb + XH_OFF + (mg * 64 + mt * 16 + xrow) * XPIT
                                   + (ks * 16 + xkof) * 2;
                    ldsm_x4(xa[mt], xaddr);
                }
                #pragma unroll
                for (int mt = 0; mt < 4; ++mt)
                    #pragma unroll
                    for (int nt = 0; nt < 4; ++nt) {
                        mma16816(acc[mt][nt], xa[mt], &bh[nt >> 1][(nt & 1) * 2]);
                        mma16816(acc[mt][nt], xa[mt], &bl[nt >> 1][(nt & 1) * 2]);
                    }
            }
            __syncthreads();
        }

        // fold Q .* (xh + 2xl) into register partials (atomics deferred)
        #pragma unroll
        for (int mt = 0; mt < 4; ++mt) {
            int r0 = base + mg * 64 + mt * 16 + (lid >> 2);
            #pragma unroll
            for (int nt = 0; nt < 4; ++nt) {
                int j = nc * NC + ng * 32 + nt * 8 + (lid & 3) * 2;
                size_t o0 = (size_t)r0 * N_FEAT + j;
                size_t o1 = o0 + 8 * N_FEAT;
                float2 h0 = __bfloat1622float2(*(const __nv_bfloat162*)((const char*)g_Xh + o0 * 2));
                float2 l0 = __bfloat1622float2(*(const __nv_bfloat162*)((const char*)g_Xl + o0 * 2));
                float2 h1 = __bfloat1622float2(*(const __nv_bfloat162*)((const char*)g_Xh + o1 * 2));
                float2 l1 = __bfloat1622float2(*(const __nv_bfloat162*)((const char*)g_Xl + o1 * 2));
                er[mt][0] += acc[mt][nt][0] * (h0.x + l0.x) + acc[mt][nt][1] * (h0.y + l0.y);
                er[mt][1] += acc[mt][nt][2] * (h1.x + l1.x) + acc[mt][nt][3] * (h1.y + l1.y);
            }
        }
    }

    // quad-lane reduce, single smem atomic per row partial
    #pragma unroll
    for (int mt = 0; mt < 4; ++mt)
        #pragma unroll
        for (int hh = 0; hh < 2; ++hh) {
            float v = er[mt][hh];
            v += __shfl_xor_sync(0xffffffffu, v, 1);
            v += __shfl_xor_sync(0xffffffffu, v, 2);
            if ((lid & 3) == 0)
                atomicAdd(&esm[mg * 64 + mt * 16 + (lid >> 2) + hh * 8], v);
        }
    __syncthreads();

    if (tid < valid) {
        int p = base + tid;
        atomicAdd(&out[g_sidp[p]], esm[tid] * g_invn[p]);
    }
}

// ---------------- launch ----------------
extern "C" void kernel_launch(void* const* d_in, const int* in_sizes, int n_in,
                              void* d_out, int out_size) {
    const float* ps   = (const float*)d_in[0];
    const float* sp   = (const float*)d_in[1];
    const float* w    = (const float*)d_in[2];
    const int*   spec = (const int*)d_in[3];
    const int*   sids = (const int*)d_in[4];
    float* out = (float*)d_out;

    int n_atoms   = in_sizes[3];
    int n_support = in_sizes[2] / N_SPECIES;

    cudaFuncSetAttribute(k_main_mma, cudaFuncAttributeMaxDynamicSharedMemorySize, SMEM_DYN);

    int pb = (N_SPECIES * n_support + 3) / 4;
    int cb = (n_atoms + 511) / 512;
    k_fuse1<<<pb + cb, 512>>>(sp, w, n_support, spec, n_atoms, out, out_size, pb);
    k_off<<<1, 32>>>();
    int sxb = (n_atoms + 15) / 16;
    k_fuse2<<<36 * N_SPECIES + sxb, 512>>>(sp, n_support, ps, spec, sids, n_atoms);

    dim3 grid((n_atoms + MT - 1) / MT, N_SPECIES);
    k_main_mma<<<grid, 256, SMEM_DYN>>>(out);
}

// round 6
// speedup vs baseline: 3.5827x; 1.0088x over previous
#include <cuda_runtime.h>
#include <cuda_bf16.h>
#include <stdint.h>

// SparseGapPerSpecies: quadratic form + warp bf16 MMA, symmetry-reduced.
//   A_s = Y_s^T diag(w/|y|^2) Y_s (symmetric) -> bf16 hi+lo
//   x'Ax = xh'A(xh+2xl) + O(2^-16)  => Q = Xh*(Ah+Al): 2 GEMM terms
//   e_atom = rowdot(Q, xh + 2xl)/|x|^2 ; energy = segment_sum
// Launch plan (ncu profiles launch #4): fuse1, off, fuse2, MAIN.

#define N_SPECIES   4
#define N_FEAT      512
#define MAX_ATOMS   100352
#define MAX_SUPPORT 1024
#define MT          128
#define NC          128
#define KC          64

__device__ __nv_bfloat16 g_Ah[N_SPECIES * N_FEAT * N_FEAT];  // [s][k][n]
__device__ __nv_bfloat16 g_Al[N_SPECIES * N_FEAT * N_FEAT];
__device__ __nv_bfloat16 g_Xh[(size_t)MAX_ATOMS * N_FEAT];   // sorted by species
__device__ __nv_bfloat16 g_Xl[(size_t)MAX_ATOMS * N_FEAT];   // holds 2*xl
__device__ float g_invn[MAX_ATOMS];
__device__ int   g_sidp[MAX_ATOMS];
__device__ float g_c[N_SPECIES * MAX_SUPPORT];
__device__ int   g_cnt[N_SPECIES];        // zero-init; k_off resets after use
__device__ int   g_off[N_SPECIES + 1];
__device__ int   g_cur[N_SPECIES];

// ---------------- PTX helpers ----------------
__device__ __forceinline__ uint32_t smem_u32(const void* p) {
    uint32_t a;
    asm("{ .reg .u64 t; cvta.to.shared.u64 t, %1; cvt.u32.u64 %0, t; }" : "=r"(a) : "l"(p));
    return a;
}
__device__ __forceinline__ void cpasync16(uint32_t dst, const void* src) {
    asm volatile("cp.async.cg.shared.global [%0], [%1], 16;" :: "r"(dst), "l"(src) : "memory");
}
#define CP_COMMIT() asm volatile("cp.async.commit_group;" ::: "memory")

__device__ __forceinline__ void ldsm_x4(uint32_t* r, uint32_t a) {
    asm volatile("ldmatrix.sync.aligned.m8n8.x4.shared.b16 {%0,%1,%2,%3}, [%4];"
                 : "=r"(r[0]), "=r"(r[1]), "=r"(r[2]), "=r"(r[3]) : "r"(a));
}
__device__ __forceinline__ void ldsm_x4t(uint32_t* r, uint32_t a) {
    asm volatile("ldmatrix.sync.aligned.m8n8.x4.trans.shared.b16 {%0,%1,%2,%3}, [%4];"
                 : "=r"(r[0]), "=r"(r[1]), "=r"(r[2]), "=r"(r[3]) : "r"(a));
}
__device__ __forceinline__ void mma16816(float* c, const uint32_t* a, const uint32_t* b) {
    asm volatile("mma.sync.aligned.m16n8k16.row.col.f32.bf16.bf16.f32 "
                 "{%0,%1,%2,%3},{%4,%5,%6,%7},{%8,%9},{%0,%1,%2,%3};"
                 : "+f"(c[0]), "+f"(c[1]), "+f"(c[2]), "+f"(c[3])
                 : "r"(a[0]), "r"(a[1]), "r"(a[2]), "r"(a[3]), "r"(b[0]), "r"(b[1]));
}
__device__ __forceinline__ uint32_t pkbf(float a, float b) {
    __nv_bfloat162 t = __floats2bfloat162_rn(a, b);
    return *(uint32_t*)&t;
}

// ---------------- launch 1: prep_c (4 pts/block) || countz ----------------
__global__ __launch_bounds__(512) void k_fuse1(const float* __restrict__ sp,
                                               const float* __restrict__ w,
                                               int n_support,
                                               const int* __restrict__ spc, int n,
                                               float* out, int n_out, int pb) {
    int bx = blockIdx.x;
    if (bx < pb) {
        // prep_c: 4 support points per block, 128 threads each
        __shared__ float r[4][4];
        int g = threadIdx.x >> 7, st = threadIdx.x & 127;
        int pt = bx * 4 + g;
        int total = N_SPECIES * n_support;
        float acc = 0.f;
        if (pt < total) {
            const float* y = sp + (size_t)pt * N_FEAT;
            #pragma unroll
            for (int t = 0; t < 4; ++t) { float v = y[st + t * 128]; acc += v * v; }
        }
        #pragma unroll
        for (int o = 16; o; o >>= 1) acc += __shfl_xor_sync(0xffffffffu, acc, o);
        if ((st & 31) == 0) r[g][st >> 5] = acc;
        __syncthreads();
        if (st == 0 && pt < total) {
            int s = pt / n_support, m = pt % n_support;
            g_c[s * MAX_SUPPORT + m] = w[pt] / (r[g][0] + r[g][1] + r[g][2] + r[g][3]);
        }
    } else {
        int i = (bx - pb) * 512 + threadIdx.x;
        if (i < n) atomicAdd(&g_cnt[spc[i]], 1);
        if (i < n_out) out[i] = 0.f;
    }
}

// ---------------- launch 2: offsets (+ reset counters for replay) ----------------
__global__ void k_off() {
    if (threadIdx.x == 0) {
        int acc = 0;
        for (int s = 0; s < N_SPECIES; ++s) {
            g_off[s] = acc; g_cur[s] = acc; acc += g_cnt[s]; g_cnt[s] = 0;
        }
        g_off[N_SPECIES] = acc;
    }
}

// ---------------- launch 3: computeA (144 blocks) || scatterX ----------------
__global__ __launch_bounds__(512) void k_fuse2(const float* __restrict__ sp, int n_support,
                                               const float* __restrict__ ps,
                                               const int* __restrict__ spc,
                                               const int* __restrict__ sids, int n) {
    int bx = blockIdx.x;
    if (bx < 36 * N_SPECIES) {
        // ---- computeA: A = Y' diag(c) Y, upper-tri 64x64 tile + mirror ----
        __shared__ float Yi[16][64];
        __shared__ float Yj[16][64];
        int s = bx / 36;
        int t = bx % 36;
        int bi = 0;
        { int rowlen = 8; while (t >= rowlen) { t -= rowlen; rowlen--; bi++; } }
        int bj = bi + t;
        int i0 = bi * 64, j0 = bj * 64;

        int tid = threadIdx.x;
        int ty = tid >> 4, tx = tid & 15;     // 32 x 16 threads, 2x4 acc
        float acc[2][4];
        #pragma unroll
        for (int a = 0; a < 2; ++a)
            #pragma unroll
            for (int b = 0; b < 4; ++b) acc[a][b] = 0.f;

        const float* Y = sp + (size_t)s * n_support * N_FEAT;
        const float* c = g_c + s * MAX_SUPPORT;

        for (int m0 = 0; m0 < n_support; m0 += 16) {
            #pragma unroll
            for (int it = 0; it < 2; ++it) {
                int idx = it * 512 + tid;
                int kk = idx >> 6, col = idx & 63;
                int m = m0 + kk;
                float yi = 0.f, yj = 0.f, cm = 0.f;
                if (m < n_support) {
                    cm = c[m];
                    yi = Y[(size_t)m * N_FEAT + i0 + col];
                    yj = Y[(size_t)m * N_FEAT + j0 + col];
                }
                Yi[kk][col] = cm * yi;
                Yj[kk][col] = yj;
            }
            __syncthreads();
            #pragma unroll
            for (int kk = 0; kk < 16; ++kk) {
                float a0 = Yi[kk][ty * 2], a1 = Yi[kk][ty * 2 + 1];
                float b[4];
                #pragma unroll
                for (int jj = 0; jj < 4; ++jj) b[jj] = Yj[kk][tx * 4 + jj];
                #pragma unroll
                for (int jj = 0; jj < 4; ++jj) { acc[0][jj] += a0 * b[jj]; acc[1][jj] += a1 * b[jj]; }
            }
            __syncthreads();
        }
        #pragma unroll
        for (int ii = 0; ii < 2; ++ii)
            #pragma unroll
            for (int jj = 0; jj < 4; ++jj) {
                int i = i0 + ty * 2 + ii;
                int j = j0 + tx * 4 + jj;
                float a = acc[ii][jj];
                __nv_bfloat16 h = __float2bfloat16(a);
                __nv_bfloat16 l = __float2bfloat16(a - __bfloat162float(h));
                size_t o = ((size_t)s * N_FEAT + i) * N_FEAT + j;
                g_Ah[o] = h; g_Al[o] = l;
                if (bi != bj) {
                    size_t om = ((size_t)s * N_FEAT + j) * N_FEAT + i;
                    g_Ah[om] = h; g_Al[om] = l;
                }
            }
    } else {
        // ---- scatterX: warp per atom; store xh and 2*xl; 1/|x|^2; sid ----
        int wid = threadIdx.x >> 5, lid = threadIdx.x & 31;
        int i = (bx - 36 * N_SPECIES) * 16 + wid;
        if (i >= n) return;
        int p;
        if (lid == 0) p = atomicAdd(&g_cur[spc[i]], 1);
        p = __shfl_sync(0xffffffffu, p, 0);

        const float4* src = (const float4*)(ps + (size_t)i * N_FEAT);
        float nrm = 0.f;
        #pragma unroll
        for (int t = 0; t < 4; ++t) {
            int v = lid + t * 32;
            float4 f = __ldg(src + v);
            nrm += f.x * f.x + f.y * f.y + f.z * f.z + f.w * f.w;
            float hx = __bfloat162float(__float2bfloat16(f.x));
            float hy = __bfloat162float(__float2bfloat16(f.y));
            float hz = __bfloat162float(__float2bfloat16(f.z));
            float hw = __bfloat162float(__float2bfloat16(f.w));
            uint2 h = make_uint2(pkbf(hx, hy), pkbf(hz, hw));
            uint2 l = make_uint2(pkbf(2.f * (f.x - hx), 2.f * (f.y - hy)),
                                 pkbf(2.f * (f.z - hz), 2.f * (f.w - hw)));
            size_t o = (size_t)p * N_FEAT + v * 4;
            *(uint2*)((char*)g_Xh + o * 2) = h;
            *(uint2*)((char*)g_Xl + o * 2) = l;
        }
        #pragma unroll
        for (int o = 16; o; o >>= 1) nrm += __shfl_xor_sync(0xffffffffu, nrm, o);
        if (lid == 0) { g_invn[p] = 1.f / nrm; g_sidp[p] = sids[i]; }
    }
}

// ---------------- launch 4: main MMA kernel ----------------
#define XPIT     144                     // 64 bf16 + 8 pad
#define APIT     272                     // 128 bf16 + 8 pad
#define XH_OFF   0
#define AH_OFF   (128 * XPIT)            // 18432
#define AL_OFF   (AH_OFF + 64 * APIT)    // 35840
#define BUFSZ    (AL_OFF + 64 * APIT)    // 53248
#define ESM_OFF  (2 * BUFSZ)             // 106496
#define SMEM_DYN (ESM_OFF + 512)

__global__ __launch_bounds__(256, 2) void k_main_mma(float* __restrict__ out) {
    extern __shared__ char smem[];
    const uint32_t sb = smem_u32(smem);
    float* esm = (float*)(smem + ESM_OFF);

    const int tid = threadIdx.x, wid = tid >> 5, lid = tid & 31;
    const int s = blockIdx.y;
    const int off0 = g_off[s], off1 = g_off[s + 1];
    const int base = off0 + blockIdx.x * MT;
    if (base >= off1) return;
    const int valid = min(MT, off1 - base);

    if (tid < MT) esm[tid] = 0.f;

    const int mg = wid >> 2;     // 0..1 : 64 rows each
    const int ng = wid & 3;      // 0..3 : 32 cols each

    const int xrow = (lid & 7) + ((lid >> 3) & 1) * 8;
    const int xkof = ((lid >> 4) & 1) * 8;
    const int akrow = (lid & 7) + ((lid >> 3) & 1) * 8;
    const int anof = ((lid >> 4) & 1) * 8;

    float er[4][2];
    #pragma unroll
    for (int a = 0; a < 4; ++a) { er[a][0] = 0.f; er[a][1] = 0.f; }

    for (int nc = 0; nc < N_FEAT / NC; ++nc) {
        float acc[4][4][4];
        #pragma unroll
        for (int a = 0; a < 4; ++a)
            #pragma unroll
            for (int b = 0; b < 4; ++b)
                #pragma unroll
                for (int q = 0; q < 4; ++q) acc[a][b][q] = 0.f;

        auto issue = [&](int kc) {
            uint32_t bufb = sb + (kc & 1) * BUFSZ;
            #pragma unroll
            for (int it = 0; it < 4; ++it) {
                int idx = it * 256 + tid;
                int r = idx >> 3, v = idx & 7;
                const char* src = (const char*)(g_Xh + (size_t)(base + r) * N_FEAT
                                                + kc * KC + v * 8);
                cpasync16(bufb + XH_OFF + r * XPIT + v * 16, src);
            }
            #pragma unroll
            for (int it = 0; it < 8; ++it) {
                int idx = it * 256 + tid;
                int sel = idx >> 10, e = idx & 1023;
                int r = e >> 4, v = e & 15;
                const __nv_bfloat16* g = sel ? g_Al : g_Ah;
                const char* src = (const char*)(g + ((size_t)s * N_FEAT + kc * KC + r) * N_FEAT
                                                + nc * NC + v * 8);
                cpasync16(bufb + (sel ? AL_OFF : AH_OFF) + r * APIT + v * 16, src);
            }
        };

        issue(0); CP_COMMIT();

        for (int kc = 0; kc < N_FEAT / KC; ++kc) {
            if (kc + 1 < N_FEAT / KC) {
                issue(kc + 1); CP_COMMIT();
                asm volatile("cp.async.wait_group 1;" ::: "memory");
            } else {
                asm volatile("cp.async.wait_group 0;" ::: "memory");
            }
            __syncthreads();

            const uint32_t bufb = sb + (kc & 1) * BUFSZ;
            #pragma unroll
            for (int ks = 0; ks < KC / 16; ++ks) {
                uint32_t bh[2][4], bl[2][4];
                #pragma unroll
                for (int t = 0; t < 2; ++t) {
                    uint32_t aa = bufb + AH_OFF + (ks * 16 + akrow) * APIT
                                + (ng * 32 + t * 16 + anof) * 2;
                    ldsm_x4t(bh[t], aa);
                    ldsm_x4t(bl[t], aa + (AL_OFF - AH_OFF));
                }
                uint32_t xa[4][4];
                #pragma unroll
                for (int mt = 0; mt < 4; ++mt) {
                    uint32_t xaddr = bufb + XH_OFF + (mg * 64 + mt * 16 + xrow) * XPIT
                                   + (ks * 16 + xkof) * 2;
                    ldsm_x4(xa[mt], xaddr);
                }
                #pragma unroll
                for (int mt = 0; mt < 4; ++mt)
                    #pragma unroll
                    for (int nt = 0; nt < 4; ++nt) {
                        mma16816(acc[mt][nt], xa[mt], &bh[nt >> 1][(nt & 1) * 2]);
                        mma16816(acc[mt][nt], xa[mt], &bl[nt >> 1][(nt & 1) * 2]);
                    }
            }
            __syncthreads();
        }

        // fold Q .* (xh + 2xl) into register partials (atomics deferred)
        #pragma unroll
        for (int mt = 0; mt < 4; ++mt) {
            int r0 = base + mg * 64 + mt * 16 + (lid >> 2);
            #pragma unroll
            for (int nt = 0; nt < 4; ++nt) {
                int j = nc * NC + ng * 32 + nt * 8 + (lid & 3) * 2;
                size_t o0 = (size_t)r0 * N_FEAT + j;
                size_t o1 = o0 + 8 * N_FEAT;
                float2 h0 = __bfloat1622float2(*(const __nv_bfloat162*)((const char*)g_Xh + o0 * 2));
                float2 l0 = __bfloat1622float2(*(const __nv_bfloat162*)((const char*)g_Xl + o0 * 2));
                float2 h1 = __bfloat1622float2(*(const __nv_bfloat162*)((const char*)g_Xh + o1 * 2));
                float2 l1 = __bfloat1622float2(*(const __nv_bfloat162*)((const char*)g_Xl + o1 * 2));
                er[mt][0] += acc[mt][nt][0] * (h0.x + l0.x) + acc[mt][nt][1] * (h0.y + l0.y);
                er[mt][1] += acc[mt][nt][2] * (h1.x + l1.x) + acc[mt][nt][3] * (h1.y + l1.y);
            }
        }
    }

    // quad-lane reduce, single smem atomic per row partial
    #pragma unroll
    for (int mt = 0; mt < 4; ++mt)
        #pragma unroll
        for (int hh = 0; hh < 2; ++hh) {
            float v = er[mt][hh];
            v += __shfl_xor_sync(0xffffffffu, v, 1);
            v += __shfl_xor_sync(0xffffffffu, v, 2);
            if ((lid & 3) == 0)
                atomicAdd(&esm[mg * 64 + mt * 16 + (lid >> 2) + hh * 8], v);
        }
    __syncthreads();

    if (tid < valid) {
        int p = base + tid;
        atomicAdd(&out[g_sidp[p]], esm[tid] * g_invn[p]);
    }
}

// ---------------- launch ----------------
extern "C" void kernel_launch(void* const* d_in, const int* in_sizes, int n_in,
                              void* d_out, int out_size) {
    const float* ps   = (const float*)d_in[0];
    const float* sp   = (const float*)d_in[1];
    const float* w    = (const float*)d_in[2];
    const int*   spec = (const int*)d_in[3];
    const int*   sids = (const int*)d_in[4];
    float* out = (float*)d_out;

    int n_atoms   = in_sizes[3];
    int n_support = in_sizes[2] / N_SPECIES;

    cudaFuncSetAttribute(k_main_mma, cudaFuncAttributeMaxDynamicSharedMemorySize, SMEM_DYN);

    int pb = (N_SPECIES * n_support + 3) / 4;
    int cb = (n_atoms + 511) / 512;
    k_fuse1<<<pb + cb, 512>>>(sp, w, n_support, spec, n_atoms, out, out_size, pb);
    k_off<<<1, 32>>>();
    int sxb = (n_atoms + 15) / 16;
    k_fuse2<<<36 * N_SPECIES + sxb, 512>>>(sp, n_support, ps, spec, sids, n_atoms);

    dim3 grid((n_atoms + MT - 1) / MT, N_SPECIES);
    k_main_mma<<<grid, 256, SMEM_DYN>>>(out);
}